// round 2
// baseline (speedup 1.0000x reference)
#include <cuda_runtime.h>

#define D_DIM 2048
#define E_DIM 64
#define BR 128
#define DK 32
#define NT 256

// scratch for deterministic cross-block load reduction (max 512 blocks)
__device__ float g_partial[512 * E_DIM];

static __device__ __forceinline__ unsigned long long pack2(float lo, float hi) {
    unsigned long long r;
    asm("mov.b64 %0, {%1, %2};" : "=l"(r) : "f"(lo), "f"(hi));
    return r;
}
static __device__ __forceinline__ void unpack2(unsigned long long v, float& lo, float& hi) {
    asm("mov.b64 {%0, %1}, %2;" : "=f"(lo), "=f"(hi) : "l"(v));
}
static __device__ __forceinline__ void fma2(unsigned long long& d, unsigned long long a, unsigned long long b) {
    asm("fma.rn.f32x2 %0, %1, %2, %0;" : "+l"(d) : "l"(a), "l"(b));
}

__global__ __launch_bounds__(NT) void router_kernel(
    const float* __restrict__ x, const float* __restrict__ W,
    const float* __restrict__ bias,
    float* __restrict__ mask_out, float* __restrict__ prob_out)
{
    __shared__ float xs[BR][DK + 1];     // +1 pad: conflict-free column reads
    __shared__ float ws[DK][E_DIM];

    const int tid = threadIdx.x;
    const int tx = tid & 7;              // expert group (8 experts each)
    const int ty = tid >> 3;             // row group (4 rows each)
    const int row0 = blockIdx.x * BR;
    const float* xblk = x + (size_t)row0 * D_DIM;

    unsigned long long acc2[4][4];       // 4 rows x 4 f32x2 pairs (8 experts)
#pragma unroll
    for (int i = 0; i < 4; i++)
#pragma unroll
        for (int j = 0; j < 4; j++) acc2[i][j] = 0ULL;

    for (int k0 = 0; k0 < D_DIM; k0 += DK) {
        // load x tile: 128 x 32 floats, float4 per thread x4
#pragma unroll
        for (int p = 0; p < 4; p++) {
            int r = (tid >> 3) + p * 32;
            int c = (tid & 7) * 4;
            float4 v = *reinterpret_cast<const float4*>(xblk + (size_t)r * D_DIM + k0 + c);
            xs[r][c] = v.x; xs[r][c + 1] = v.y; xs[r][c + 2] = v.z; xs[r][c + 3] = v.w;
        }
        // load W tile: 32 x 64 floats
#pragma unroll
        for (int q = 0; q < 2; q++) {
            int id = tid * 2 + q;
            int kk = id >> 4;
            int c = (id & 15) * 4;
            *reinterpret_cast<float4*>(&ws[kk][c]) =
                *reinterpret_cast<const float4*>(W + (size_t)(k0 + kk) * E_DIM + c);
        }
        __syncthreads();
#pragma unroll
        for (int kk = 0; kk < DK; kk++) {
            // LDS.128 directly into f32x2 operand pairs (no repack movs)
            ulonglong2 wa = *reinterpret_cast<const ulonglong2*>(&ws[kk][tx * 8]);
            ulonglong2 wb = *reinterpret_cast<const ulonglong2*>(&ws[kk][tx * 8 + 4]);
#pragma unroll
            for (int i = 0; i < 4; i++) {
                float xv = xs[ty * 4 + i][kk];
                unsigned long long xx = pack2(xv, xv);
                fma2(acc2[i][0], xx, wa.x);
                fma2(acc2[i][1], xx, wa.y);
                fma2(acc2[i][2], xx, wb.x);
                fma2(acc2[i][3], xx, wb.y);
            }
        }
        __syncthreads();
    }

    float bv[8];
#pragma unroll
    for (int j = 0; j < 8; j++) bv[j] = bias[tx * 8 + j];

    float loadacc[8];
#pragma unroll
    for (int j = 0; j < 8; j++) loadacc[j] = 0.f;

#pragma unroll
    for (int i = 0; i < 4; i++) {
        float lg[8];
#pragma unroll
        for (int j = 0; j < 4; j++) {
            float lo, hi;
            unpack2(acc2[i][j], lo, hi);
            lg[2 * j]     = lo + bv[2 * j];
            lg[2 * j + 1] = hi + bv[2 * j + 1];
        }
        // stable softmax over 64 experts held 8-per-lane across an 8-lane group
        float m = lg[0];
#pragma unroll
        for (int j = 1; j < 8; j++) m = fmaxf(m, lg[j]);
#pragma unroll
        for (int d = 1; d < 8; d <<= 1) m = fmaxf(m, __shfl_xor_sync(0xffffffffu, m, d));
        float ev[8], ssum = 0.f;
#pragma unroll
        for (int j = 0; j < 8; j++) { ev[j] = __expf(lg[j] - m); ssum += ev[j]; }
#pragma unroll
        for (int d = 1; d < 8; d <<= 1) ssum += __shfl_xor_sync(0xffffffffu, ssum, d);
        float inv = 1.0f / ssum;

        // top-3 via 3 rounds of argmax (lowest-index tie-break, matches lax.top_k)
        unsigned chosenMask = 0u;
#pragma unroll
        for (int t = 0; t < 3; t++) {
            float bvv = -3.0e38f; int bi = 1 << 20;
#pragma unroll
            for (int j = 0; j < 8; j++) {
                float v = ((chosenMask >> j) & 1u) ? -3.0e38f : lg[j];
                if (v > bvv) { bvv = v; bi = tx * 8 + j; }
            }
#pragma unroll
            for (int d = 1; d < 8; d <<= 1) {
                float ov = __shfl_xor_sync(0xffffffffu, bvv, d);
                int   oi = __shfl_xor_sync(0xffffffffu, bi, d);
                if (ov > bvv || (ov == bvv && oi < bi)) { bvv = ov; bi = oi; }
            }
            if ((bi >> 3) == tx) chosenMask |= 1u << (bi & 7);
        }

        float pr[8], mk[8];
#pragma unroll
        for (int j = 0; j < 8; j++) {
            pr[j] = ev[j] * inv;
            mk[j] = ((chosenMask >> j) & 1u) ? 1.0f : 0.0f;
            loadacc[j] += pr[j];
        }
        size_t base = ((size_t)(row0 + ty * 4 + i)) * E_DIM + tx * 8;
        *reinterpret_cast<float4*>(prob_out + base)     = make_float4(pr[0], pr[1], pr[2], pr[3]);
        *reinterpret_cast<float4*>(prob_out + base + 4) = make_float4(pr[4], pr[5], pr[6], pr[7]);
        *reinterpret_cast<float4*>(mask_out + base)     = make_float4(mk[0], mk[1], mk[2], mk[3]);
        *reinterpret_cast<float4*>(mask_out + base + 4) = make_float4(mk[4], mk[5], mk[6], mk[7]);
    }

    // deterministic fixed-order per-block reduction of load (reuse ws smem)
    float (*shred)[E_DIM] = ws;
#pragma unroll
    for (int j = 0; j < 8; j++) shred[ty][tx * 8 + j] = loadacc[j];
    __syncthreads();
    if (tid < E_DIM) {
        float s = 0.f;
#pragma unroll
        for (int t = 0; t < 32; t++) s += shred[t][tid];
        g_partial[blockIdx.x * E_DIM + tid] = s;
    }
}

__global__ void reduce_kernel(float* __restrict__ imp, float* __restrict__ ld, int nblk) {
    __shared__ float sm[256];
    int e = blockIdx.x, t = threadIdx.x;
    sm[t] = (t < nblk) ? g_partial[(size_t)t * E_DIM + e] : 0.f;
    __syncthreads();
    for (int s = 128; s > 0; s >>= 1) {
        if (t < s) sm[t] += sm[t + s];
        __syncthreads();
    }
    if (t == 0) { imp[e] = sm[0]; ld[e] = sm[0]; }
}

extern "C" void kernel_launch(void* const* d_in, const int* in_sizes, int n_in,
                              void* d_out, int out_size) {
    const float* x    = (const float*)d_in[0];
    const float* W    = (const float*)d_in[1];
    const float* bias = (const float*)d_in[2];
    float* out = (float*)d_out;

    int N = in_sizes[0] / D_DIM;                 // 32768
    float* mask_out = out;
    float* prob_out = out + (size_t)N * E_DIM;
    float* imp      = out + 2 * (size_t)N * E_DIM;
    float* ld       = imp + E_DIM;

    int nblk = N / BR;                           // 256
    router_kernel<<<nblk, NT>>>(x, W, bias, mask_out, prob_out);
    reduce_kernel<<<E_DIM, 256>>>(imp, ld, nblk);
}

// round 3
// speedup vs baseline: 1.0005x; 1.0005x over previous
#include <cuda_runtime.h>

#define D_DIM 2048
#define E_DIM 64
#define BR 128
#define DK 32
#define NT 256

// scratch for deterministic cross-block load reduction (max 512 blocks)
__device__ float g_partial[512 * E_DIM];

static __device__ __forceinline__ unsigned long long pack2(float lo, float hi) {
    unsigned long long r;
    asm("mov.b64 %0, {%1, %2};" : "=l"(r) : "f"(lo), "f"(hi));
    return r;
}
static __device__ __forceinline__ void unpack2(unsigned long long v, float& lo, float& hi) {
    asm("mov.b64 {%0, %1}, %2;" : "=f"(lo), "=f"(hi) : "l"(v));
}
static __device__ __forceinline__ void fma2(unsigned long long& d, unsigned long long a, unsigned long long b) {
    asm("fma.rn.f32x2 %0, %1, %2, %0;" : "+l"(d) : "l"(a), "l"(b));
}

__global__ __launch_bounds__(NT) void router_kernel(
    const float* __restrict__ x, const float* __restrict__ W,
    const float* __restrict__ bias,
    float* __restrict__ mask_out, float* __restrict__ prob_out)
{
    __shared__ float xs[BR][DK + 1];     // +1 pad: conflict-free column reads
    __shared__ float ws[DK][E_DIM];

    const int tid = threadIdx.x;
    const int tx = tid & 7;              // expert group (8 experts each)
    const int ty = tid >> 3;             // row group (4 rows each)
    const int row0 = blockIdx.x * BR;
    const float* xblk = x + (size_t)row0 * D_DIM;

    unsigned long long acc2[4][4];       // 4 rows x 4 f32x2 pairs (8 experts)
#pragma unroll
    for (int i = 0; i < 4; i++)
#pragma unroll
        for (int j = 0; j < 4; j++) acc2[i][j] = 0ULL;

    for (int k0 = 0; k0 < D_DIM; k0 += DK) {
        // load x tile: 128 x 32 floats, float4 per thread x4
#pragma unroll
        for (int p = 0; p < 4; p++) {
            int r = (tid >> 3) + p * 32;
            int c = (tid & 7) * 4;
            float4 v = *reinterpret_cast<const float4*>(xblk + (size_t)r * D_DIM + k0 + c);
            xs[r][c] = v.x; xs[r][c + 1] = v.y; xs[r][c + 2] = v.z; xs[r][c + 3] = v.w;
        }
        // load W tile: 32 x 64 floats
#pragma unroll
        for (int q = 0; q < 2; q++) {
            int id = tid * 2 + q;
            int kk = id >> 4;
            int c = (id & 15) * 4;
            *reinterpret_cast<float4*>(&ws[kk][c]) =
                *reinterpret_cast<const float4*>(W + (size_t)(k0 + kk) * E_DIM + c);
        }
        __syncthreads();
#pragma unroll
        for (int kk = 0; kk < DK; kk++) {
            // LDS.128 directly into f32x2 operand pairs (no repack movs)
            ulonglong2 wa = *reinterpret_cast<const ulonglong2*>(&ws[kk][tx * 8]);
            ulonglong2 wb = *reinterpret_cast<const ulonglong2*>(&ws[kk][tx * 8 + 4]);
#pragma unroll
            for (int i = 0; i < 4; i++) {
                float xv = xs[ty * 4 + i][kk];
                unsigned long long xx = pack2(xv, xv);
                fma2(acc2[i][0], xx, wa.x);
                fma2(acc2[i][1], xx, wa.y);
                fma2(acc2[i][2], xx, wb.x);
                fma2(acc2[i][3], xx, wb.y);
            }
        }
        __syncthreads();
    }

    float bv[8];
#pragma unroll
    for (int j = 0; j < 8; j++) bv[j] = bias[tx * 8 + j];

    float loadacc[8];
#pragma unroll
    for (int j = 0; j < 8; j++) loadacc[j] = 0.f;

#pragma unroll
    for (int i = 0; i < 4; i++) {
        float lg[8];
#pragma unroll
        for (int j = 0; j < 4; j++) {
            float lo, hi;
            unpack2(acc2[i][j], lo, hi);
            lg[2 * j]     = lo + bv[2 * j];
            lg[2 * j + 1] = hi + bv[2 * j + 1];
        }
        // stable softmax over 64 experts held 8-per-lane across an 8-lane group
        float m = lg[0];
#pragma unroll
        for (int j = 1; j < 8; j++) m = fmaxf(m, lg[j]);
#pragma unroll
        for (int d = 1; d < 8; d <<= 1) m = fmaxf(m, __shfl_xor_sync(0xffffffffu, m, d));
        float ev[8], ssum = 0.f;
#pragma unroll
        for (int j = 0; j < 8; j++) { ev[j] = __expf(lg[j] - m); ssum += ev[j]; }
#pragma unroll
        for (int d = 1; d < 8; d <<= 1) ssum += __shfl_xor_sync(0xffffffffu, ssum, d);
        float inv = 1.0f / ssum;

        // top-3 via 3 rounds of argmax (lowest-index tie-break, matches lax.top_k)
        unsigned chosenMask = 0u;
#pragma unroll
        for (int t = 0; t < 3; t++) {
            float bvv = -3.0e38f; int bi = 1 << 20;
#pragma unroll
            for (int j = 0; j < 8; j++) {
                float v = ((chosenMask >> j) & 1u) ? -3.0e38f : lg[j];
                if (v > bvv) { bvv = v; bi = tx * 8 + j; }
            }
#pragma unroll
            for (int d = 1; d < 8; d <<= 1) {
                float ov = __shfl_xor_sync(0xffffffffu, bvv, d);
                int   oi = __shfl_xor_sync(0xffffffffu, bi, d);
                if (ov > bvv || (ov == bvv && oi < bi)) { bvv = ov; bi = oi; }
            }
            if ((bi >> 3) == tx) chosenMask |= 1u << (bi & 7);
        }

        float pr[8], mk[8];
#pragma unroll
        for (int j = 0; j < 8; j++) {
            pr[j] = ev[j] * inv;
            mk[j] = ((chosenMask >> j) & 1u) ? 1.0f : 0.0f;
            loadacc[j] += pr[j];
        }
        size_t base = ((size_t)(row0 + ty * 4 + i)) * E_DIM + tx * 8;
        *reinterpret_cast<float4*>(prob_out + base)     = make_float4(pr[0], pr[1], pr[2], pr[3]);
        *reinterpret_cast<float4*>(prob_out + base + 4) = make_float4(pr[4], pr[5], pr[6], pr[7]);
        *reinterpret_cast<float4*>(mask_out + base)     = make_float4(mk[0], mk[1], mk[2], mk[3]);
        *reinterpret_cast<float4*>(mask_out + base + 4) = make_float4(mk[4], mk[5], mk[6], mk[7]);
    }

    // deterministic fixed-order per-block reduction of load (reuse ws smem)
    float (*shred)[E_DIM] = ws;
#pragma unroll
    for (int j = 0; j < 8; j++) shred[ty][tx * 8 + j] = loadacc[j];
    __syncthreads();
    if (tid < E_DIM) {
        float s = 0.f;
#pragma unroll
        for (int t = 0; t < 32; t++) s += shred[t][tid];
        g_partial[blockIdx.x * E_DIM + tid] = s;
    }
}

__global__ void reduce_kernel(float* __restrict__ imp, float* __restrict__ ld, int nblk) {
    __shared__ float sm[256];
    int e = blockIdx.x, t = threadIdx.x;
    sm[t] = (t < nblk) ? g_partial[(size_t)t * E_DIM + e] : 0.f;
    __syncthreads();
    for (int s = 128; s > 0; s >>= 1) {
        if (t < s) sm[t] += sm[t + s];
        __syncthreads();
    }
    if (t == 0) { imp[e] = sm[0]; ld[e] = sm[0]; }
}

extern "C" void kernel_launch(void* const* d_in, const int* in_sizes, int n_in,
                              void* d_out, int out_size) {
    const float* x    = (const float*)d_in[0];
    const float* W    = (const float*)d_in[1];
    const float* bias = (const float*)d_in[2];
    float* out = (float*)d_out;

    int N = in_sizes[0] / D_DIM;                 // 32768
    float* mask_out = out;
    float* prob_out = out + (size_t)N * E_DIM;
    float* imp      = out + 2 * (size_t)N * E_DIM;
    float* ld       = imp + E_DIM;

    int nblk = N / BR;                           // 256
    router_kernel<<<nblk, NT>>>(x, W, bias, mask_out, prob_out);
    reduce_kernel<<<E_DIM, 256>>>(imp, ld, nblk);
}

// round 4
// speedup vs baseline: 1.4559x; 1.4551x over previous
#include <cuda_runtime.h>

#define D_DIM 2048
#define E_DIM 64
#define BR 128
#define DK 32
#define NT 256
#define NTILE (D_DIM / DK)   // 64

// scratch for deterministic cross-block load reduction (max 512 blocks)
__device__ float g_partial[512 * E_DIM];
__device__ unsigned int g_counter = 0;

static __device__ __forceinline__ unsigned long long pack2(float lo, float hi) {
    unsigned long long r;
    asm("mov.b64 %0, {%1, %2};" : "=l"(r) : "f"(lo), "f"(hi));
    return r;
}
static __device__ __forceinline__ void unpack2(unsigned long long v, float& lo, float& hi) {
    asm("mov.b64 {%0, %1}, %2;" : "=f"(lo), "=f"(hi) : "l"(v));
}
static __device__ __forceinline__ void fma2(unsigned long long& d, unsigned long long a, unsigned long long b) {
    asm("fma.rn.f32x2 %0, %1, %2, %0;" : "+l"(d) : "l"(a), "l"(b));
}

__global__ __launch_bounds__(NT, 2) void router_fused_kernel(
    const float* __restrict__ x, const float* __restrict__ W,
    const float* __restrict__ bias,
    float* __restrict__ mask_out, float* __restrict__ prob_out,
    float* __restrict__ imp, float* __restrict__ ld)
{
    // x tile duplicated into both lanes of a float2 -> LDS.64 yields a ready
    // packed f32x2 operand (no mov.b64). Pad 1 float2/row: row stride 33*8B,
    // rows {i, i+4, i+8, i+12} land in distinct double-banks -> conflict-free.
    __shared__ float2 xs2[BR][DK + 1];
    // W tile with chunk-permuted layout: expert chunk c16 (4 experts) stored at
    // float offset (c16>>1)*4 + (c16&1)*32, so the 8 "wa" LDS.128 chunks sit at
    // bytes 0,16,...,112 (8 distinct bank quads) -> conflict-free.
    __shared__ float ws2[DK][E_DIM];
    __shared__ float psum[4][E_DIM];
    __shared__ unsigned int s_last;

    const int tid = threadIdx.x;
    const int tx = tid & 7;              // expert group (8 experts each)
    const int ty = tid >> 3;             // 0..31
    const int row0 = blockIdx.x * BR;
    const float* xb = x + (size_t)row0 * D_DIM;

    // accumulators: 4 rows x 4 f32x2 pairs (8 experts), bias folded into init
    unsigned long long acc2[4][4];
    {
        float b0[8];
#pragma unroll
        for (int j = 0; j < 8; j++) b0[j] = bias[tx * 8 + j];
#pragma unroll
        for (int i = 0; i < 4; i++)
#pragma unroll
            for (int j = 0; j < 4; j++)
                acc2[i][j] = pack2(b0[2 * j], b0[2 * j + 1]);
    }

    // software pipeline: tile t in smem while tile t+1 streams into registers
    float4 xr[4], wr[2];
#pragma unroll
    for (int p = 0; p < 4; p++)
        xr[p] = *reinterpret_cast<const float4*>(xb + (size_t)(ty + p * 32) * D_DIM + tx * 4);
#pragma unroll
    for (int q = 0; q < 2; q++) {
        int id = tid * 2 + q;
        wr[q] = *reinterpret_cast<const float4*>(W + (size_t)(id >> 4) * E_DIM + (id & 15) * 4);
    }

    for (int t = 0; t < NTILE; t++) {
        // commit registers -> smem
#pragma unroll
        for (int p = 0; p < 4; p++) {
            int r = ty + p * 32;
            float2* xrow = xs2[r] + tx * 4;
            xrow[0] = make_float2(xr[p].x, xr[p].x);
            xrow[1] = make_float2(xr[p].y, xr[p].y);
            xrow[2] = make_float2(xr[p].z, xr[p].z);
            xrow[3] = make_float2(xr[p].w, xr[p].w);
        }
#pragma unroll
        for (int q = 0; q < 2; q++) {
            int id = tid * 2 + q;
            int kk = id >> 4, c16 = id & 15;
            int dst = (c16 >> 1) * 4 + (c16 & 1) * 32;
            *reinterpret_cast<float4*>(&ws2[kk][dst]) = wr[q];
        }
        __syncthreads();

        // issue next tile's global loads early (hidden behind compute)
        if (t + 1 < NTILE) {
            const int k0 = (t + 1) * DK;
#pragma unroll
            for (int p = 0; p < 4; p++)
                xr[p] = *reinterpret_cast<const float4*>(xb + (size_t)(ty + p * 32) * D_DIM + k0 + tx * 4);
#pragma unroll
            for (int q = 0; q < 2; q++) {
                int id = tid * 2 + q;
                wr[q] = *reinterpret_cast<const float4*>(W + (size_t)(k0 + (id >> 4)) * E_DIM + (id & 15) * 4);
            }
        }

#pragma unroll
        for (int kk = 0; kk < DK; kk++) {
            ulonglong2 wa = *reinterpret_cast<const ulonglong2*>(&ws2[kk][tx * 4]);       // experts 8tx..8tx+3
            ulonglong2 wb = *reinterpret_cast<const ulonglong2*>(&ws2[kk][32 + tx * 4]);  // experts 8tx+4..8tx+7
#pragma unroll
            for (int i = 0; i < 4; i++) {
                unsigned long long xx =
                    *reinterpret_cast<const unsigned long long*>(&xs2[ty * 4 + i][kk]);
                fma2(acc2[i][0], xx, wa.x);
                fma2(acc2[i][1], xx, wa.y);
                fma2(acc2[i][2], xx, wb.x);
                fma2(acc2[i][3], xx, wb.y);
            }
        }
        __syncthreads();
    }

    // ---------------- epilogue: softmax + top-3 + outputs ----------------
    float loadacc[8];
#pragma unroll
    for (int j = 0; j < 8; j++) loadacc[j] = 0.f;

#pragma unroll
    for (int i = 0; i < 4; i++) {
        float lg[8];
#pragma unroll
        for (int j = 0; j < 4; j++) unpack2(acc2[i][j], lg[2 * j], lg[2 * j + 1]);

        // stable softmax over 64 experts held 8-per-lane across an 8-lane group
        float m = lg[0];
#pragma unroll
        for (int j = 1; j < 8; j++) m = fmaxf(m, lg[j]);
#pragma unroll
        for (int d = 1; d < 8; d <<= 1) m = fmaxf(m, __shfl_xor_sync(0xffffffffu, m, d));
        float ev[8], ssum = 0.f;
#pragma unroll
        for (int j = 0; j < 8; j++) { ev[j] = __expf(lg[j] - m); ssum += ev[j]; }
#pragma unroll
        for (int d = 1; d < 8; d <<= 1) ssum += __shfl_xor_sync(0xffffffffu, ssum, d);
        float inv = 1.0f / ssum;

        // top-3 via 3 rounds of argmax (lowest-index tie-break = lax.top_k)
        unsigned chosenMask = 0u;
#pragma unroll
        for (int t = 0; t < 3; t++) {
            float bvv = -3.0e38f; int bi = 1 << 20;
#pragma unroll
            for (int j = 0; j < 8; j++) {
                float v = ((chosenMask >> j) & 1u) ? -3.0e38f : lg[j];
                if (v > bvv) { bvv = v; bi = tx * 8 + j; }
            }
#pragma unroll
            for (int d = 1; d < 8; d <<= 1) {
                float ov = __shfl_xor_sync(0xffffffffu, bvv, d);
                int   oi = __shfl_xor_sync(0xffffffffu, bi, d);
                if (ov > bvv || (ov == bvv && oi < bi)) { bvv = ov; bi = oi; }
            }
            if ((bi >> 3) == tx) chosenMask |= 1u << (bi & 7);
        }

        float pr[8], mk[8];
#pragma unroll
        for (int j = 0; j < 8; j++) {
            pr[j] = ev[j] * inv;
            mk[j] = ((chosenMask >> j) & 1u) ? 1.0f : 0.0f;
            loadacc[j] += pr[j];
        }
        size_t base = ((size_t)(row0 + ty * 4 + i)) * E_DIM + tx * 8;
        *reinterpret_cast<float4*>(prob_out + base)     = make_float4(pr[0], pr[1], pr[2], pr[3]);
        *reinterpret_cast<float4*>(prob_out + base + 4) = make_float4(pr[4], pr[5], pr[6], pr[7]);
        *reinterpret_cast<float4*>(mask_out + base)     = make_float4(mk[0], mk[1], mk[2], mk[3]);
        *reinterpret_cast<float4*>(mask_out + base + 4) = make_float4(mk[4], mk[5], mk[6], mk[7]);
    }

    // ---------------- deterministic per-block load reduction -------------
    float (*shred)[E_DIM] = ws2;   // reuse W tile smem
#pragma unroll
    for (int j = 0; j < 8; j++) shred[ty][tx * 8 + j] = loadacc[j];
    __syncthreads();
    if (tid < E_DIM) {
        float s = 0.f;
#pragma unroll
        for (int t = 0; t < 32; t++) s += shred[t][tid];
        g_partial[(size_t)blockIdx.x * E_DIM + tid] = s;
    }
    __threadfence();

    // -------- last-block fused final reduction (deterministic order) -----
    if (tid == 0)
        s_last = (atomicAdd(&g_counter, 1u) == gridDim.x - 1) ? 1u : 0u;
    __syncthreads();
    if (s_last) {
        const int nblk = (int)gridDim.x;
        const int per = (nblk + 3) >> 2;
        const int e = tid & 63, part = tid >> 6;
        float s = 0.f;
        const int b0 = part * per;
        const int b1 = (b0 + per < nblk) ? b0 + per : nblk;
        for (int b = b0; b < b1; b++)
            s += __ldcg(&g_partial[(size_t)b * E_DIM + e]);
        psum[part][e] = s;
        __syncthreads();
        if (tid < E_DIM) {
            float tot = ((psum[0][tid] + psum[1][tid]) + psum[2][tid]) + psum[3][tid];
            imp[tid] = tot;
            ld[tid]  = tot;
        }
        if (tid == 0) g_counter = 0u;   // reset for next graph replay
    }
}

extern "C" void kernel_launch(void* const* d_in, const int* in_sizes, int n_in,
                              void* d_out, int out_size) {
    const float* x    = (const float*)d_in[0];
    const float* W    = (const float*)d_in[1];
    const float* bias = (const float*)d_in[2];
    float* out = (float*)d_out;

    int N = in_sizes[0] / D_DIM;                 // 32768
    float* mask_out = out;
    float* prob_out = out + (size_t)N * E_DIM;
    float* imp      = out + 2 * (size_t)N * E_DIM;
    float* ld       = imp + E_DIM;

    int nblk = N / BR;                           // 256
    router_fused_kernel<<<nblk, NT>>>(x, W, bias, mask_out, prob_out, imp, ld);
}

// round 5
// speedup vs baseline: 2.1491x; 1.4762x over previous
#include <cuda_runtime.h>

#define D_DIM 2048
#define E_DIM 64
#define BR 256
#define DK 32
#define NT 256
#define NTILE (D_DIM / DK)   // 64

__device__ float g_partial[512 * E_DIM];
__device__ unsigned int g_counter = 0;

static __device__ __forceinline__ unsigned long long pack2(float lo, float hi) {
    unsigned long long r;
    asm("mov.b64 %0, {%1, %2};" : "=l"(r) : "f"(lo), "f"(hi));
    return r;
}
static __device__ __forceinline__ void unpack2(unsigned long long v, float& lo, float& hi) {
    asm("mov.b64 {%0, %1}, %2;" : "=f"(lo), "=f"(hi) : "l"(v));
}
static __device__ __forceinline__ void fma2(unsigned long long& d, unsigned long long a, unsigned long long b) {
    asm("fma.rn.f32x2 %0, %1, %2, %0;" : "+l"(d) : "l"(a), "l"(b));
}

__global__ __launch_bounds__(NT, 1) void router_fused_kernel(
    const float* __restrict__ x, const float* __restrict__ W,
    const float* __restrict__ bias,
    float* __restrict__ mask_out, float* __restrict__ prob_out,
    float* __restrict__ imp, float* __restrict__ ld)
{
    // x transposed: xs[k][row], row column XOR-swizzled by 4*((k>>2)&7).
    // -> transpose STS conflict-free, mainloop LDS.128 conflict-free, 16B aligned.
    __shared__ float xs[DK][BR];            // 32 KB
    // W tile chunk-permuted: chunk c16 -> float offset (c16>>1)*4 + (c16&1)*32,
    // so wa/wb LDS.128 chunks hit 8 distinct bank quads.
    __shared__ float ws[DK][E_DIM];         // 8 KB
    __shared__ float psum[4][E_DIM];
    __shared__ unsigned int s_last;

    const int tid = threadIdx.x;
    const int tx = tid & 7;                 // expert group (8 experts)
    const int ty = tid >> 3;                // 0..31 -> rows ty*8..ty*8+7
    const int row0 = blockIdx.x * BR;
    const float* xb = x + (size_t)row0 * D_DIM;

    // accumulators: 8 rows x 4 f32x2 pairs (8 experts), bias folded in
    unsigned long long acc2[8][4];
    {
        float b0[8];
#pragma unroll
        for (int j = 0; j < 8; j++) b0[j] = bias[tx * 8 + j];
#pragma unroll
        for (int i = 0; i < 8; i++)
#pragma unroll
            for (int j = 0; j < 4; j++)
                acc2[i][j] = pack2(b0[2 * j], b0[2 * j + 1]);
    }

    // software pipeline registers
    float4 xr[8], wr[2];
#pragma unroll
    for (int p = 0; p < 8; p++)
        xr[p] = *reinterpret_cast<const float4*>(xb + (size_t)(ty + p * 32) * D_DIM + tx * 4);
#pragma unroll
    for (int q = 0; q < 2; q++) {
        int id = tid * 2 + q;
        wr[q] = *reinterpret_cast<const float4*>(W + (size_t)(id >> 4) * E_DIM + (id & 15) * 4);
    }

    for (int t = 0; t < NTILE; t++) {
        // commit x transposed with swizzle: phys col = r ^ (4*tx), k = tx*4+j
#pragma unroll
        for (int p = 0; p < 8; p++) {
            int r = ty + p * 32;
            int pc = r ^ (tx * 4);
            xs[tx * 4 + 0][pc] = xr[p].x;
            xs[tx * 4 + 1][pc] = xr[p].y;
            xs[tx * 4 + 2][pc] = xr[p].z;
            xs[tx * 4 + 3][pc] = xr[p].w;
        }
#pragma unroll
        for (int q = 0; q < 2; q++) {
            int id = tid * 2 + q;
            int kk = id >> 4, c16 = id & 15;
            int dst = (c16 >> 1) * 4 + (c16 & 1) * 32;
            *reinterpret_cast<float4*>(&ws[kk][dst]) = wr[q];
        }
        __syncthreads();

        // next tile's global loads (hidden behind compute)
        if (t + 1 < NTILE) {
            const int k0 = (t + 1) * DK;
#pragma unroll
            for (int p = 0; p < 8; p++)
                xr[p] = *reinterpret_cast<const float4*>(xb + (size_t)(ty + p * 32) * D_DIM + k0 + tx * 4);
#pragma unroll
            for (int q = 0; q < 2; q++) {
                int id = tid * 2 + q;
                wr[q] = *reinterpret_cast<const float4*>(W + (size_t)(k0 + (id >> 4)) * E_DIM + (id & 15) * 4);
            }
        }

#pragma unroll
        for (int kk = 0; kk < DK; kk++) {
            ulonglong2 wa = *reinterpret_cast<const ulonglong2*>(&ws[kk][tx * 4]);       // e 8tx..+3
            ulonglong2 wb = *reinterpret_cast<const ulonglong2*>(&ws[kk][32 + tx * 4]);  // e 8tx+4..+7
            const int swz = 4 * ((kk >> 2) & 7);
            float4 xa = *reinterpret_cast<const float4*>(&xs[kk][(ty * 8) ^ swz]);       // rows ty*8..+3
            float4 xb4 = *reinterpret_cast<const float4*>(&xs[kk][(ty * 8 + 4) ^ swz]);  // rows ty*8+4..+7
            const float xv[8] = {xa.x, xa.y, xa.z, xa.w, xb4.x, xb4.y, xb4.z, xb4.w};
#pragma unroll
            for (int i = 0; i < 8; i++) {
                unsigned long long xx = pack2(xv[i], xv[i]);
                fma2(acc2[i][0], xx, wa.x);
                fma2(acc2[i][1], xx, wa.y);
                fma2(acc2[i][2], xx, wb.x);
                fma2(acc2[i][3], xx, wb.y);
            }
        }
        __syncthreads();
    }

    // ---------------- epilogue: softmax + top-3 + outputs ----------------
    float loadacc[8];
#pragma unroll
    for (int j = 0; j < 8; j++) loadacc[j] = 0.f;

#pragma unroll
    for (int i = 0; i < 8; i++) {
        float lg[8];
#pragma unroll
        for (int j = 0; j < 4; j++) unpack2(acc2[i][j], lg[2 * j], lg[2 * j + 1]);

        float m = lg[0];
#pragma unroll
        for (int j = 1; j < 8; j++) m = fmaxf(m, lg[j]);
#pragma unroll
        for (int d = 1; d < 8; d <<= 1) m = fmaxf(m, __shfl_xor_sync(0xffffffffu, m, d));
        float ev[8], ssum = 0.f;
#pragma unroll
        for (int j = 0; j < 8; j++) { ev[j] = __expf(lg[j] - m); ssum += ev[j]; }
#pragma unroll
        for (int d = 1; d < 8; d <<= 1) ssum += __shfl_xor_sync(0xffffffffu, ssum, d);
        float inv = 1.0f / ssum;

        unsigned chosenMask = 0u;
#pragma unroll
        for (int t = 0; t < 3; t++) {
            float bvv = -3.0e38f; int bi = 1 << 20;
#pragma unroll
            for (int j = 0; j < 8; j++) {
                float v = ((chosenMask >> j) & 1u) ? -3.0e38f : lg[j];
                if (v > bvv) { bvv = v; bi = tx * 8 + j; }
            }
#pragma unroll
            for (int d = 1; d < 8; d <<= 1) {
                float ov = __shfl_xor_sync(0xffffffffu, bvv, d);
                int   oi = __shfl_xor_sync(0xffffffffu, bi, d);
                if (ov > bvv || (ov == bvv && oi < bi)) { bvv = ov; bi = oi; }
            }
            if ((bi >> 3) == tx) chosenMask |= 1u << (bi & 7);
        }

        float pr[8], mk[8];
#pragma unroll
        for (int j = 0; j < 8; j++) {
            pr[j] = ev[j] * inv;
            mk[j] = ((chosenMask >> j) & 1u) ? 1.0f : 0.0f;
            loadacc[j] += pr[j];
        }
        size_t base = ((size_t)(row0 + ty * 8 + i)) * E_DIM + tx * 8;
        *reinterpret_cast<float4*>(prob_out + base)     = make_float4(pr[0], pr[1], pr[2], pr[3]);
        *reinterpret_cast<float4*>(prob_out + base + 4) = make_float4(pr[4], pr[5], pr[6], pr[7]);
        *reinterpret_cast<float4*>(mask_out + base)     = make_float4(mk[0], mk[1], mk[2], mk[3]);
        *reinterpret_cast<float4*>(mask_out + base + 4) = make_float4(mk[4], mk[5], mk[6], mk[7]);
    }

    // ---------------- deterministic per-block load reduction -------------
    float (*shred)[E_DIM] = ws;
#pragma unroll
    for (int j = 0; j < 8; j++) shred[ty][tx * 8 + j] = loadacc[j];
    __syncthreads();
    if (tid < E_DIM) {
        float s = 0.f;
#pragma unroll
        for (int t = 0; t < 32; t++) s += shred[t][tid];
        g_partial[(size_t)blockIdx.x * E_DIM + tid] = s;
    }
    __threadfence();

    if (tid == 0)
        s_last = (atomicAdd(&g_counter, 1u) == gridDim.x - 1) ? 1u : 0u;
    __syncthreads();
    if (s_last) {
        const int nblk = (int)gridDim.x;
        const int per = (nblk + 3) >> 2;
        const int e = tid & 63, part = tid >> 6;
        float s = 0.f;
        const int b0 = part * per;
        const int b1 = (b0 + per < nblk) ? b0 + per : nblk;
        for (int b = b0; b < b1; b++)
            s += __ldcg(&g_partial[(size_t)b * E_DIM + e]);
        psum[part][e] = s;
        __syncthreads();
        if (tid < E_DIM) {
            float tot = ((psum[0][tid] + psum[1][tid]) + psum[2][tid]) + psum[3][tid];
            imp[tid] = tot;
            ld[tid]  = tot;
        }
        if (tid == 0) g_counter = 0u;
    }
}

extern "C" void kernel_launch(void* const* d_in, const int* in_sizes, int n_in,
                              void* d_out, int out_size) {
    const float* x    = (const float*)d_in[0];
    const float* W    = (const float*)d_in[1];
    const float* bias = (const float*)d_in[2];
    float* out = (float*)d_out;

    int N = in_sizes[0] / D_DIM;                 // 32768
    float* mask_out = out;
    float* prob_out = out + (size_t)N * E_DIM;
    float* imp      = out + 2 * (size_t)N * E_DIM;
    float* ld       = imp + E_DIM;

    int nblk = N / BR;                           // 128
    router_fused_kernel<<<nblk, NT>>>(x, W, bias, mask_out, prob_out, imp, ld);
}